// round 11
// baseline (speedup 1.0000x reference)
#include <cuda_runtime.h>
#include <math.h>

#define BB 8
#define VV 3
#define HH 512
#define WW 640
#define NPIX (HH*WW)
#define NQUADS (NPIX/4)            // 81920
#define NPAIR (VV*VV)
#define TPB 256
#define QPT 4                      // float4 quads per thread
#define GX 80                      // 80*256 = 20480 quads = exactly 128 rows per pass
#define QSTRIDE (GX*TPB)
#define ROWSTEP 128
#define QROW (WW/4)                // 160
#define NBLOCKS (GX*BB*VV)

#define FMAGIC 8388610.0f          // 2^23 + 2
#define IMAGIC 0x4B000002

__device__ double   g_num[BB*NPAIR];
__device__ double   g_den[BB*NPAIR];
__device__ unsigned g_count;

__device__ __forceinline__ void mat4mul(const float* A, const float* Bm, float* C) {
#pragma unroll
    for (int r = 0; r < 4; r++)
#pragma unroll
        for (int c = 0; c < 4; c++) {
            float s = 0.0f;
#pragma unroll
            for (int k = 0; k < 4; k++) s = fmaf(A[r*4+k], Bm[k*4+c], s);
            C[r*4+c] = s;
        }
}

__device__ __forceinline__ void compute_P(const float* __restrict__ K,
                                          const float* __restrict__ RT,
                                          int b, int i, int j, float* out) {
    const float* Kb  = K  + b*16;
    const float* RTi = RT + (b*VV + i)*16;
    const float* RTj = RT + (b*VV + j)*16;

    float Kinv[16] = {0};
    float fx = Kb[0], fy = Kb[5], cx = Kb[2], cy = Kb[6];
    Kinv[0]  = 1.0f/fx;  Kinv[2]  = -cx/fx;
    Kinv[5]  = 1.0f/fy;  Kinv[6]  = -cy/fy;
    Kinv[10] = 1.0f;     Kinv[15] = 1.0f;

    float Ri[16] = {0};
    Ri[0] = RTi[0]; Ri[1] = RTi[4]; Ri[2]  = RTi[8];
    Ri[4] = RTi[1]; Ri[5] = RTi[5]; Ri[6]  = RTi[9];
    Ri[8] = RTi[2]; Ri[9] = RTi[6]; Ri[10] = RTi[10];
    float tx = RTi[3], ty = RTi[7], tz = RTi[11];
    Ri[3]  = -(Ri[0]*tx + Ri[1]*ty + Ri[2]*tz);
    Ri[7]  = -(Ri[4]*tx + Ri[5]*ty + Ri[6]*tz);
    Ri[11] = -(Ri[8]*tx + Ri[9]*ty + Ri[10]*tz);
    Ri[15] = 1.0f;

    float M1[16], M2[16], Pf[16];
    mat4mul(RTj, Ri, M1);
    mat4mul(M1, Kinv, M2);
    mat4mul(Kb, M2, Pf);
#pragma unroll
    for (int k = 0; k < 12; k++) out[k] = Pf[k];
}

// Extract element (sel in [0,3]) from a float4 with selects (no dynamic index).
__device__ __forceinline__ float f4_extract(const float4& f, int sel) {
    const float lo = (sel & 2) ? f.z : f.x;
    const float hi = (sel & 2) ? f.w : f.y;
    return (sel & 1) ? hi : lo;
}

__global__ void __launch_bounds__(TPB, 6)
loss_kernel(const float* __restrict__ pred, const float* __restrict__ K,
            const float* __restrict__ RT, float* __restrict__ out) {
    const int b = blockIdx.y, i = blockIdx.z;

    __shared__ float sP[VV][12];
    if (threadIdx.x < VV)
        compute_P(K, RT, b, i, threadIdx.x, sP[threadIdx.x]);
    __syncthreads();

    const float* __restrict__ di  = pred + (size_t)(b*VV + i)*NPIX;
    const float* __restrict__ dj0 = pred + (size_t)(b*VV + 0)*NPIX;

    const int q0  = blockIdx.x*TPB + threadIdx.x;
    const int yy0 = q0 / QROW;
    const float xf0 = (float)((q0 - yy0*QROW) * 4);

    const float XMAX = 639.0f, YMAX = 511.0f;
    const float SXI  = 640.0f/639.0f, SYI = 512.0f/511.0f;

    float num[VV] = {0.f, 0.f, 0.f};
    float den[VV] = {0.f, 0.f, 0.f};

#pragma unroll
    for (int k = 0; k < QPT; k++) {
        const int q = q0 + k*QSTRIDE;
        const float4 dvq = __ldg((const float4*)di + q);
        const float yf = (float)(yy0 + k*ROWSTEP);
        const float* dptr = (const float*)&dvq;

#pragma unroll
        for (int j = 0; j < VV; j++) {
            const float P00 = sP[j][0], P01 = sP[j][1], P02 = sP[j][2],  P03 = sP[j][3];
            const float P10 = sP[j][4], P11 = sP[j][5], P12 = sP[j][6],  P13 = sP[j][7];
            const float P20 = sP[j][8], P21 = sP[j][9], P22 = sP[j][10], P23 = sP[j][11];
            const float* __restrict__ dj = dj0 + (size_t)j*NPIX;

            float ax = fmaf(P00, xf0, fmaf(P01, yf, P02));
            float ay = fmaf(P10, xf0, fmaf(P11, yf, P12));
            float az = fmaf(P20, xf0, fmaf(P21, yf, P22));
            float ln = 0.0f, ld = 0.0f;
#pragma unroll
            for (int l = 0; l < 4; l++) {
                const float d  = dptr[l];
                const float px = fmaf(d, ax, P03);   // homogeneous w == 1 exactly
                const float py = fmaf(d, ay, P13);
                if (px >= 0.0f && px <= XMAX && py >= 0.0f && py <= YMAX) {
                    const float pz = fmaf(d, az, P23);
                    const float ux = fmaf(px, SXI, -1.0f);   // ix - 0.5
                    const float uy = fmaf(py, SYI, -1.0f);
                    const float tmx = ux + FMAGIC;
                    const float tmy = uy + FMAGIC;
                    const int   x0 = __float_as_int(tmx) - IMAGIC;   // floor(ix) in [-1,639]
                    const int   y0 = __float_as_int(tmy) - IMAGIC;   // floor(iy) in [-1,511]
                    const float x0f = tmx - FMAGIC;
                    const float y0f = tmy - FMAGIC;
                    const float wx1 = (ux - x0f) + 0.5f;
                    const float wy1 = (uy - y0f) + 0.5f;
                    const int base = y0*WW + x0;
                    const bool vx0 = (x0 >= 0);
                    const bool vx1 = (x0 != WW-1);
                    const bool vy0 = (y0 >= 0);
                    const bool vy1 = (y0 != HH-1);
                    const int idx = base & 3;            // same for top & bottom (WW%4==0)

                    // ---- top row: one aligned float4 covers c00 (+ c10 unless idx==3)
                    int eT = base & ~3;
                    eT = eT < 0 ? 0 : (eT > NPIX-4 ? NPIX-4 : eT);
                    float4 fT = make_float4(0.f, 0.f, 0.f, 0.f);
                    if (vy0) fT = __ldg((const float4*)dj + (eT >> 2));
                    float c00 = (vx0 && vy0) ? f4_extract(fT, idx) : 0.0f;
                    float c10;
                    if (idx == 3) c10 = (vx1 && vy0) ? __ldg(dj + base + 1) : 0.0f;
                    else          c10 = (vx1 && vy0) ? f4_extract(fT, idx + 1) : 0.0f;

                    // ---- bottom row
                    const int base2 = base + WW;
                    int eB = base2 & ~3;
                    eB = eB < 0 ? 0 : (eB > NPIX-4 ? NPIX-4 : eB);
                    float4 fB = make_float4(0.f, 0.f, 0.f, 0.f);
                    if (vy1) fB = __ldg((const float4*)dj + (eB >> 2));
                    float c01 = (vx0 && vy1) ? f4_extract(fB, idx) : 0.0f;
                    float c11;
                    if (idx == 3) c11 = (vx1 && vy1) ? __ldg(dj + base2 + 1) : 0.0f;
                    else          c11 = (vx1 && vy1) ? f4_extract(fB, idx + 1) : 0.0f;

                    const float top = fmaf(wx1, c10 - c00, c00);
                    const float bot = fmaf(wx1, c11 - c01, c01);
                    const float warped = fmaf(wy1, bot - top, top);
                    ln += fabsf(warped - pz);
                    ld += 1.0f;
                }
                ax += P00;
                ay += P10;
                az += P20;
            }
            num[j] += ln; den[j] += ld;
        }
    }

    // block reduce 6 scalars
    __shared__ float sred[2*VV][TPB/32];
    const int warp = threadIdx.x >> 5, lane = threadIdx.x & 31;
#pragma unroll
    for (int j = 0; j < VV; j++) {
        float n = num[j], dn = den[j];
#pragma unroll
        for (int o = 16; o > 0; o >>= 1) {
            n  += __shfl_xor_sync(0xFFFFFFFFu, n,  o);
            dn += __shfl_xor_sync(0xFFFFFFFFu, dn, o);
        }
        if (lane == 0) { sred[2*j][warp] = n; sred[2*j+1][warp] = dn; }
    }
    __syncthreads();
    if (threadIdx.x < 2*VV) {
        float s = 0.0f;
#pragma unroll
        for (int w = 0; w < TPB/32; w++) s += sred[threadIdx.x][w];
        const int j = threadIdx.x >> 1;
        const int p = (b*VV + i)*VV + j;
        if ((threadIdx.x & 1) == 0) atomicAdd(&g_num[p], (double)s);
        else                        atomicAdd(&g_den[p], (double)s);
    }
    __syncthreads();

    // last-block finalize
    __shared__ bool s_last;
    if (threadIdx.x == 0) {
        __threadfence();
        s_last = (atomicAdd(&g_count, 1u) == (unsigned)(NBLOCKS - 1));
    }
    __syncthreads();
    if (s_last && threadIdx.x == 0) {
        double t = 0.0;
#pragma unroll
        for (int pp = 0; pp < NPAIR; pp++) {
            double n = 0.0, dn = 0.0;
#pragma unroll
            for (int bb = 0; bb < BB; bb++) {
                n  += g_num[bb*NPAIR + pp];
                dn += g_den[bb*NPAIR + pp];
            }
            t += n / (dn > 1.0 ? dn : 1.0);
        }
        out[0] = (float)t;
#pragma unroll
        for (int pp = 0; pp < BB*NPAIR; pp++) { g_num[pp] = 0.0; g_den[pp] = 0.0; }
        __threadfence();
        g_count = 0u;
    }
}

extern "C" void kernel_launch(void* const* d_in, const int* in_sizes, int n_in,
                              void* d_out, int out_size) {
    const float* pred = (const float*)d_in[0];   // (B,V,H,W)
    const float* K    = (const float*)d_in[1];   // (B,4,4)
    const float* RT   = (const float*)d_in[2];   // (B,V,4,4)
    loss_kernel<<<dim3(GX, BB, VV), TPB>>>(pred, K, RT, (float*)d_out);
}

// round 12
// speedup vs baseline: 2.5473x; 2.5473x over previous
#include <cuda_runtime.h>
#include <math.h>

#define BB 8
#define VV 3
#define HH 512
#define WW 640
#define NPIX (HH*WW)
#define NQUADS (NPIX/4)            // 81920
#define NPAIR (VV*VV)
#define TPB 256
#define QPT 4                      // float4 quads per thread
#define GX 80                      // 80*256 = 20480 quads = exactly 128 rows per pass
#define QSTRIDE (GX*TPB)
#define ROWSTEP 128
#define QROW (WW/4)                // 160
#define NBLOCKS (GX*BB*VV)

#define FMAGIC 8388610.0f          // 2^23 + 2
#define IMAGIC 0x4B000002

__device__ double   g_num[BB*NPAIR];
__device__ double   g_den[BB*NPAIR];
__device__ unsigned g_count;

__device__ __forceinline__ void mat4mul(const float* A, const float* Bm, float* C) {
#pragma unroll
    for (int r = 0; r < 4; r++)
#pragma unroll
        for (int c = 0; c < 4; c++) {
            float s = 0.0f;
#pragma unroll
            for (int k = 0; k < 4; k++) s = fmaf(A[r*4+k], Bm[k*4+c], s);
            C[r*4+c] = s;
        }
}

__device__ __forceinline__ void compute_P(const float* __restrict__ K,
                                          const float* __restrict__ RT,
                                          int b, int i, int j, float* out) {
    const float* Kb  = K  + b*16;
    const float* RTi = RT + (b*VV + i)*16;
    const float* RTj = RT + (b*VV + j)*16;

    float Kinv[16] = {0};
    float fx = Kb[0], fy = Kb[5], cx = Kb[2], cy = Kb[6];
    Kinv[0]  = 1.0f/fx;  Kinv[2]  = -cx/fx;
    Kinv[5]  = 1.0f/fy;  Kinv[6]  = -cy/fy;
    Kinv[10] = 1.0f;     Kinv[15] = 1.0f;

    float Ri[16] = {0};
    Ri[0] = RTi[0]; Ri[1] = RTi[4]; Ri[2]  = RTi[8];
    Ri[4] = RTi[1]; Ri[5] = RTi[5]; Ri[6]  = RTi[9];
    Ri[8] = RTi[2]; Ri[9] = RTi[6]; Ri[10] = RTi[10];
    float tx = RTi[3], ty = RTi[7], tz = RTi[11];
    Ri[3]  = -(Ri[0]*tx + Ri[1]*ty + Ri[2]*tz);
    Ri[7]  = -(Ri[4]*tx + Ri[5]*ty + Ri[6]*tz);
    Ri[11] = -(Ri[8]*tx + Ri[9]*ty + Ri[10]*tz);
    Ri[15] = 1.0f;

    float M1[16], M2[16], Pf[16];
    mat4mul(RTj, Ri, M1);
    mat4mul(M1, Kinv, M2);
    mat4mul(Kb, M2, Pf);
#pragma unroll
    for (int k = 0; k < 12; k++) out[k] = Pf[k];
}

__global__ void __launch_bounds__(TPB, 5)
loss_kernel(const float* __restrict__ pred, const float* __restrict__ K,
            const float* __restrict__ RT, float* __restrict__ out) {
    const int b = blockIdx.y, i = blockIdx.z;

    __shared__ float sP[VV][12];
    if (threadIdx.x < VV)
        compute_P(K, RT, b, i, threadIdx.x, sP[threadIdx.x]);
    __syncthreads();

    const float* __restrict__ di  = pred + (size_t)(b*VV + i)*NPIX;
    const float* __restrict__ dj0 = pred + (size_t)(b*VV + 0)*NPIX;

    const int q0  = blockIdx.x*TPB + threadIdx.x;
    const int yy0 = q0 / QROW;
    const float xf0 = (float)((q0 - yy0*QROW) * 4);

    const float XMAX = 639.0f, YMAX = 511.0f;
    const float SXI  = 640.0f/639.0f, SYI = 512.0f/511.0f;

    float num[VV] = {0.f, 0.f, 0.f};
    float den[VV] = {0.f, 0.f, 0.f};

#pragma unroll
    for (int k = 0; k < QPT; k++) {
        const int q = q0 + k*QSTRIDE;
        const float4 dvq = __ldg((const float4*)di + q);
        const float yf = (float)(yy0 + k*ROWSTEP);
        const float* dptr = (const float*)&dvq;

#pragma unroll
        for (int j = 0; j < VV; j++) {
            const float P00 = sP[j][0], P01 = sP[j][1], P02 = sP[j][2],  P03 = sP[j][3];
            const float P10 = sP[j][4], P11 = sP[j][5], P12 = sP[j][6],  P13 = sP[j][7];
            const float P20 = sP[j][8], P21 = sP[j][9], P22 = sP[j][10], P23 = sP[j][11];
            const float* __restrict__ dj = dj0 + (size_t)j*NPIX;

            float ax = fmaf(P00, xf0, fmaf(P01, yf, P02));
            float ay = fmaf(P10, xf0, fmaf(P11, yf, P12));
            float az = fmaf(P20, xf0, fmaf(P21, yf, P22));
            float ln = 0.0f, ld = 0.0f;
#pragma unroll
            for (int l = 0; l < 4; l++) {
                const float d  = dptr[l];
                const float px = fmaf(d, ax, P03);   // homogeneous w == 1 exactly
                const float py = fmaf(d, ay, P13);
                const bool in = (px >= 0.0f && px <= XMAX && py >= 0.0f && py <= YMAX);

                // flat (branch-free) gather path; all loads predicated on full validity
                const float pz = fmaf(d, az, P23);
                const float ux = fmaf(px, SXI, -1.0f);   // ix - 0.5
                const float uy = fmaf(py, SYI, -1.0f);
                const float tmx = ux + FMAGIC;
                const float tmy = uy + FMAGIC;
                const int   x0 = __float_as_int(tmx) - IMAGIC;   // floor(ix)
                const int   y0 = __float_as_int(tmy) - IMAGIC;   // floor(iy)
                const float x0f = tmx - FMAGIC;
                const float y0f = tmy - FMAGIC;
                const float wx1 = (ux - x0f) + 0.5f;
                const float wy1 = (uy - y0f) + 0.5f;
                const int base = y0*WW + x0;
                const bool vx0 = in && (x0 >= 0);       // in => x0 <= W-1
                const bool vx1 = in && (x0 >= -1) && (x0 < WW-1);
                const bool vy0 = (y0 >= 0);             // in => y0 <= H-1
                const bool vy1 = (y0 < HH-1);
                const float c00 = (vx0 && vy0) ? __ldg(dj + base)        : 0.0f;
                const float c10 = (vx1 && vy0) ? __ldg(dj + base + 1)    : 0.0f;
                const float c01 = (vx0 && vy1) ? __ldg(dj + base + WW)   : 0.0f;
                const float c11 = (vx1 && vy1) ? __ldg(dj + base + WW+1) : 0.0f;
                const float top = fmaf(wx1, c10 - c00, c00);
                const float bot = fmaf(wx1, c11 - c01, c01);
                const float warped = fmaf(wy1, bot - top, top);
                const float msk = in ? 1.0f : 0.0f;
                ln = fmaf(msk, fabsf(warped - pz), ln);
                ld += msk;

                ax += P00;
                ay += P10;
                az += P20;
            }
            num[j] += ln; den[j] += ld;
        }
    }

    // block reduce 6 scalars
    __shared__ float sred[2*VV][TPB/32];
    const int warp = threadIdx.x >> 5, lane = threadIdx.x & 31;
#pragma unroll
    for (int j = 0; j < VV; j++) {
        float n = num[j], dn = den[j];
#pragma unroll
        for (int o = 16; o > 0; o >>= 1) {
            n  += __shfl_xor_sync(0xFFFFFFFFu, n,  o);
            dn += __shfl_xor_sync(0xFFFFFFFFu, dn, o);
        }
        if (lane == 0) { sred[2*j][warp] = n; sred[2*j+1][warp] = dn; }
    }
    __syncthreads();
    if (threadIdx.x < 2*VV) {
        float s = 0.0f;
#pragma unroll
        for (int w = 0; w < TPB/32; w++) s += sred[threadIdx.x][w];
        const int j = threadIdx.x >> 1;
        const int p = (b*VV + i)*VV + j;
        if ((threadIdx.x & 1) == 0) atomicAdd(&g_num[p], (double)s);
        else                        atomicAdd(&g_den[p], (double)s);
    }
    __syncthreads();

    // last-block finalize
    __shared__ bool s_last;
    if (threadIdx.x == 0) {
        __threadfence();
        s_last = (atomicAdd(&g_count, 1u) == (unsigned)(NBLOCKS - 1));
    }
    __syncthreads();
    if (s_last && threadIdx.x == 0) {
        double t = 0.0;
#pragma unroll
        for (int pp = 0; pp < NPAIR; pp++) {
            double n = 0.0, dn = 0.0;
#pragma unroll
            for (int bb = 0; bb < BB; bb++) {
                n  += g_num[bb*NPAIR + pp];
                dn += g_den[bb*NPAIR + pp];
            }
            t += n / (dn > 1.0 ? dn : 1.0);
        }
        out[0] = (float)t;
#pragma unroll
        for (int pp = 0; pp < BB*NPAIR; pp++) { g_num[pp] = 0.0; g_den[pp] = 0.0; }
        __threadfence();
        g_count = 0u;
    }
}

extern "C" void kernel_launch(void* const* d_in, const int* in_sizes, int n_in,
                              void* d_out, int out_size) {
    const float* pred = (const float*)d_in[0];   // (B,V,H,W)
    const float* K    = (const float*)d_in[1];   // (B,4,4)
    const float* RT   = (const float*)d_in[2];   // (B,V,4,4)
    loss_kernel<<<dim3(GX, BB, VV), TPB>>>(pred, K, RT, (float*)d_out);
}